// round 3
// baseline (speedup 1.0000x reference)
#include <cuda_runtime.h>
#include <cuda_bf16.h>
#include <cstdint>
#include <cstddef>

// ---------------------------------------------------------------------------
// RotatE scoring on base-target sm_103 (no tcgen05 on base target!):
//   C[b,n] = sum_d( sre[b,d]*ent_re[n,d] + sim[b,d]*ent_im[n,d] )
// bf16x3 split GEMM (hi*hi + hi*lo + lo*hi, fp32 accum) via mma.sync m16n8k16.
//   M=1024 (batch), N=100000 (entities), K=2048 (re||im concat).
// prep_A: gather + sincos + rotate + bf16 hi/lo split -> g_A_hi/g_A_lo
// prep_B: entity tables f32 -> bf16 hi/lo split      -> g_B_hi/g_B_lo
// gemm  : 128x128 tile, cp.async double-buffer, ldmatrix + mma.sync
//
// R2 fix: B fragments use NON-trans ldmatrix. B is stored [n][k]; a non-trans
// m8n8 load of that block already yields the mma "col" B fragment
// (lane l -> (k=(l%4)*2+i, n=l/4)). The previous .trans load swapped k/n.
// ---------------------------------------------------------------------------

#define N_ENT   100000
#define DIM     1024
#define BATCH   1024
#define K2      2048

#define TILE_M  128
#define TILE_N  128
#define KC      32
#define NCH     (K2 / KC)        // 64
#define PITCH   80               // SMEM row pitch (bytes): conflict-free ldmatrix
#define TSZ     (TILE_M * PITCH) // 10240 per tile
#define STG     (4 * TSZ)        // Ah, Al, Bh, Bl
#define SMEM_DYN (2 * STG)       // 81920

// Pre-split operands (module-static device memory; no runtime allocation)
__device__ __nv_bfloat16 g_A_hi[(size_t)BATCH * K2];
__device__ __nv_bfloat16 g_A_lo[(size_t)BATCH * K2];
__device__ __nv_bfloat16 g_B_hi[(size_t)N_ENT * K2];
__device__ __nv_bfloat16 g_B_lo[(size_t)N_ENT * K2];

// ---------------------------- helpers --------------------------------------
__device__ __forceinline__ uint32_t smem_u32(const void* p) {
    uint32_t a;
    asm("{ .reg .u64 t; cvta.to.shared.u64 t, %1; cvt.u32.u64 %0, t; }"
        : "=r"(a) : "l"(p));
    return a;
}

__device__ __forceinline__ void cpasync16(uint32_t s, const void* g) {
    asm volatile("cp.async.cg.shared.global [%0], [%1], 16;"
                 :: "r"(s), "l"(__cvta_generic_to_global(g)));
}
__device__ __forceinline__ void cp_commit() {
    asm volatile("cp.async.commit_group;");
}
template <int N>
__device__ __forceinline__ void cp_wait() {
    asm volatile("cp.async.wait_group %0;" :: "n"(N));
}

__device__ __forceinline__ void ldsm4(uint32_t* r, uint32_t addr) {
    asm volatile("ldmatrix.sync.aligned.m8n8.x4.shared.b16 {%0,%1,%2,%3}, [%4];"
                 : "=r"(r[0]), "=r"(r[1]), "=r"(r[2]), "=r"(r[3]) : "r"(addr));
}

__device__ __forceinline__ void mma16816(float* c, const uint32_t* a,
                                         uint32_t b0, uint32_t b1) {
    asm volatile(
        "mma.sync.aligned.m16n8k16.row.col.f32.bf16.bf16.f32 "
        "{%0,%1,%2,%3}, {%4,%5,%6,%7}, {%8,%9}, {%0,%1,%2,%3};"
        : "+f"(c[0]), "+f"(c[1]), "+f"(c[2]), "+f"(c[3])
        : "r"(a[0]), "r"(a[1]), "r"(a[2]), "r"(a[3]), "r"(b0), "r"(b1));
}

__device__ __forceinline__ uint32_t pack2(__nv_bfloat16 a, __nv_bfloat16 b) {
    return (uint32_t)__bfloat16_as_ushort(a) |
           ((uint32_t)__bfloat16_as_ushort(b) << 16);
}

__device__ __forceinline__ void split4(float4 v, uint2& hp, uint2& lp) {
    __nv_bfloat16 h0 = __float2bfloat16(v.x);
    __nv_bfloat16 l0 = __float2bfloat16(v.x - __bfloat162float(h0));
    __nv_bfloat16 h1 = __float2bfloat16(v.y);
    __nv_bfloat16 l1 = __float2bfloat16(v.y - __bfloat162float(h1));
    __nv_bfloat16 h2 = __float2bfloat16(v.z);
    __nv_bfloat16 l2 = __float2bfloat16(v.z - __bfloat162float(h2));
    __nv_bfloat16 h3 = __float2bfloat16(v.w);
    __nv_bfloat16 l3 = __float2bfloat16(v.w - __bfloat162float(h3));
    hp.x = pack2(h0, h1); hp.y = pack2(h2, h3);
    lp.x = pack2(l0, l1); lp.y = pack2(l2, l3);
}

// ---------------------- prep kernels ---------------------------------------
__global__ void __launch_bounds__(256)
prep_A(const int* __restrict__ e1, const int* __restrict__ r,
       const float* __restrict__ ent_re, const float* __restrict__ ent_im,
       const float* __restrict__ phase) {
    const int b = blockIdx.x;
    const int e = e1[b];
    const int rl = r[b];
    const float* hr = ent_re + (size_t)e * DIM;
    const float* hm = ent_im + (size_t)e * DIM;
    const float* ph = phase + (size_t)rl * DIM;
    for (int d = threadIdx.x; d < DIM; d += 256) {
        float a = hr[d], bb = hm[d], p = ph[d];
        float sn, cs;
        sincosf(p, &sn, &cs);
        float sre = a * cs - bb * sn;
        float sim = a * sn + bb * cs;
        __nv_bfloat16 h0 = __float2bfloat16(sre);
        __nv_bfloat16 l0 = __float2bfloat16(sre - __bfloat162float(h0));
        __nv_bfloat16 h1 = __float2bfloat16(sim);
        __nv_bfloat16 l1 = __float2bfloat16(sim - __bfloat162float(h1));
        size_t o = (size_t)b * K2 + d;
        g_A_hi[o] = h0;        g_A_lo[o] = l0;
        g_A_hi[o + DIM] = h1;  g_A_lo[o + DIM] = l1;
    }
}

__global__ void __launch_bounds__(256)
prep_B(const float* __restrict__ ent_re, const float* __restrict__ ent_im) {
    const int n = blockIdx.x;
#pragma unroll
    for (int j = 0; j < 2; ++j) {
        int idx = threadIdx.x + j * 256;            // 0..511 float4 slots
        const float* src = (idx < 256)
            ? ent_re + (size_t)n * DIM + idx * 4
            : ent_im + (size_t)n * DIM + (idx - 256) * 4;
        float4 v = *(const float4*)src;
        uint2 hp, lp;
        split4(v, hp, lp);
        size_t o = (size_t)n * K2 + (size_t)idx * 4;
        *(uint2*)(g_B_hi + o) = hp;
        *(uint2*)(g_B_lo + o) = lp;
    }
}

// ---------------------- GEMM kernel ----------------------------------------
__global__ void __launch_bounds__(256)
gemm_kernel(float* __restrict__ out) {
    extern __shared__ char smem[];
    const uint32_t sb0 = smem_u32(smem);

    const int tid = threadIdx.x;
    const int lane = tid & 31;
    const int wid = tid >> 5;
    const int wm = wid & 1;        // 2 M-blocks of 64
    const int wn = wid >> 1;       // 4 N-blocks of 32
    const int m0 = blockIdx.x * TILE_M;
    const int n0 = blockIdx.y * TILE_N;

    // cp.async addressing: each thread covers 2 rows x 16B per tile
    const int row0 = tid >> 2;     // 0..63
    const int c16 = tid & 3;

    // ldmatrix base offsets (within a stage)
    const uint32_t aRow = (uint32_t)((wm * 64 + (lane & 15)) * PITCH + (lane >> 4) * 16);
    const uint32_t bRow = (uint32_t)((wn * 32 + (lane & 15)) * PITCH + (lane >> 4) * 16);

    float acc[4][4][4];
#pragma unroll
    for (int a = 0; a < 4; ++a)
#pragma unroll
        for (int b = 0; b < 4; ++b)
#pragma unroll
            for (int c = 0; c < 4; ++c) acc[a][b][c] = 0.f;

    // ---- load one K-chunk into stage s ----
    auto load_chunk = [&](int i) {
        const uint32_t sb = sb0 + (i & 1) * STG;
        const int kc = i * KC;
#pragma unroll
        for (int j = 0; j < 2; ++j) {
            const int row = row0 + j * 64;
            const uint32_t so = (uint32_t)(row * PITCH + c16 * 16);
            const size_t ga = (size_t)(m0 + row) * K2 + kc + c16 * 8;
            cpasync16(sb + so,           g_A_hi + ga);
            cpasync16(sb + TSZ + so,     g_A_lo + ga);
            int n = n0 + row;
            if (n > N_ENT - 1) n = N_ENT - 1;
            const size_t gb = (size_t)n * K2 + kc + c16 * 8;
            cpasync16(sb + 2 * TSZ + so, g_B_hi + gb);
            cpasync16(sb + 3 * TSZ + so, g_B_lo + gb);
        }
        cp_commit();
    };

    load_chunk(0);

    for (int i = 0; i < NCH; ++i) {
        if (i + 1 < NCH) { load_chunk(i + 1); cp_wait<1>(); }
        else             { cp_wait<0>(); }
        __syncthreads();

        const uint32_t sb = sb0 + (i & 1) * STG;
#pragma unroll
        for (int kk = 0; kk < 2; ++kk) {
            const uint32_t ko = kk * 32;
            uint32_t ah[4][4], al[4][4], bh[2][4], bl[2][4];
#pragma unroll
            for (int mi = 0; mi < 4; ++mi)
                ldsm4(ah[mi], sb + aRow + mi * (16 * PITCH) + ko);
#pragma unroll
            for (int p = 0; p < 2; ++p)
                ldsm4(bh[p], sb + 2 * TSZ + bRow + p * (16 * PITCH) + ko);
            // pass 1: Ah * Bh
#pragma unroll
            for (int mi = 0; mi < 4; ++mi)
#pragma unroll
                for (int p = 0; p < 2; ++p) {
                    mma16816(acc[mi][2 * p],     ah[mi], bh[p][0], bh[p][2]);
                    mma16816(acc[mi][2 * p + 1], ah[mi], bh[p][1], bh[p][3]);
                }
            // pass 2: Ah * Bl
#pragma unroll
            for (int p = 0; p < 2; ++p)
                ldsm4(bl[p], sb + 3 * TSZ + bRow + p * (16 * PITCH) + ko);
#pragma unroll
            for (int mi = 0; mi < 4; ++mi)
#pragma unroll
                for (int p = 0; p < 2; ++p) {
                    mma16816(acc[mi][2 * p],     ah[mi], bl[p][0], bl[p][2]);
                    mma16816(acc[mi][2 * p + 1], ah[mi], bl[p][1], bl[p][3]);
                }
            // pass 3: Al * Bh
#pragma unroll
            for (int mi = 0; mi < 4; ++mi)
                ldsm4(al[mi], sb + TSZ + aRow + mi * (16 * PITCH) + ko);
#pragma unroll
            for (int mi = 0; mi < 4; ++mi)
#pragma unroll
                for (int p = 0; p < 2; ++p) {
                    mma16816(acc[mi][2 * p],     al[mi], bh[p][0], bh[p][2]);
                    mma16816(acc[mi][2 * p + 1], al[mi], bh[p][1], bh[p][3]);
                }
        }
        __syncthreads();   // protect stage before it is overwritten next iter
    }

    // ---- epilogue ----
    const int mrow = m0 + wm * 64 + (lane >> 2);
    const int ncol = n0 + wn * 32 + (lane & 3) * 2;
#pragma unroll
    for (int mi = 0; mi < 4; ++mi) {
#pragma unroll
        for (int ni = 0; ni < 4; ++ni) {
            const int col = ncol + ni * 8;
            if (col < N_ENT) {
                const int r0 = mrow + mi * 16;
                float2 v0 = make_float2(acc[mi][ni][0], acc[mi][ni][1]);
                float2 v1 = make_float2(acc[mi][ni][2], acc[mi][ni][3]);
                *(float2*)(out + (size_t)r0 * N_ENT + col) = v0;
                *(float2*)(out + (size_t)(r0 + 8) * N_ENT + col) = v1;
            }
        }
    }
}

// ---------------------------- launch ---------------------------------------
extern "C" void kernel_launch(void* const* d_in, const int* in_sizes, int n_in,
                              void* d_out, int out_size) {
    const int*   e1     = (const int*)d_in[0];
    const int*   r      = (const int*)d_in[1];
    const float* ent_re = (const float*)d_in[2];
    const float* ent_im = (const float*)d_in[3];
    const float* phase  = (const float*)d_in[4];
    float* out = (float*)d_out;

    prep_A<<<BATCH, 256>>>(e1, r, ent_re, ent_im, phase);
    prep_B<<<N_ENT, 256>>>(ent_re, ent_im);

    cudaFuncSetAttribute(gemm_kernel,
                         cudaFuncAttributeMaxDynamicSharedMemorySize, SMEM_DYN);
    // m-tiles fastest: 8 CTAs sharing one entity tile are wave-co-resident,
    // so entity data is read ~once from DRAM and reused 8x through L2.
    dim3 grid(BATCH / TILE_M, (N_ENT + TILE_N - 1) / TILE_N);
    gemm_kernel<<<grid, 256, SMEM_DYN>>>(out);
}

// round 4
// speedup vs baseline: 1.4596x; 1.4596x over previous
#include <cuda_runtime.h>
#include <cuda_fp16.h>
#include <cstdint>
#include <cstddef>

// ---------------------------------------------------------------------------
// RotatE scoring on base-target sm_103 (no tcgen05 on base target):
//   C[b,n] = sum_d( sre[b,d]*ent_re[n,d] + sim[b,d]*ent_im[n,d] )
// fp16x2 split GEMM: A = ha + la (fp16 pair, 22 mantissa bits), B = hb (fp16).
//   C ~= ha*hb + la*hb = a*hb ; dropped a*lb term ~1.5e-4 norm-rel (<1e-3).
//   M=1024, N=100000, K=2048 (re||im concat), fp32 accum via mma.sync m16n8k16.
// prep_A: gather + sincos + rotate + fp16 hi/lo split -> g_A_hi/g_A_lo
// prep_B: entity tables f32 -> fp16                  -> g_B
// gemm  : 128x128 tile, 3-stage cp.async pipeline, ldmatrix + mma.sync
//         (fragment mappings identical to the R3-validated bf16 kernel)
// ---------------------------------------------------------------------------

#define N_ENT   100000
#define DIM     1024
#define BATCH   1024
#define K2      2048

#define TILE_M  128
#define TILE_N  128
#define KC      32
#define NCH     (K2 / KC)        // 64
#define PITCH   80               // SMEM row pitch (bytes): conflict-free ldmatrix
#define TSZ     (TILE_M * PITCH) // 10240 per tile
#define STG     (3 * TSZ)        // Ah, Al, Bh -> 30720
#define NSTAGE  3
#define SMEM_DYN (NSTAGE * STG)  // 92160

__device__ __half g_A_hi[(size_t)BATCH * K2];
__device__ __half g_A_lo[(size_t)BATCH * K2];
__device__ __half g_B[(size_t)N_ENT * K2];

// ---------------------------- helpers --------------------------------------
__device__ __forceinline__ uint32_t smem_u32(const void* p) {
    uint32_t a;
    asm("{ .reg .u64 t; cvta.to.shared.u64 t, %1; cvt.u32.u64 %0, t; }"
        : "=r"(a) : "l"(p));
    return a;
}

__device__ __forceinline__ void cpasync16(uint32_t s, const void* g) {
    asm volatile("cp.async.cg.shared.global [%0], [%1], 16;"
                 :: "r"(s), "l"(__cvta_generic_to_global(g)));
}
__device__ __forceinline__ void cp_commit() {
    asm volatile("cp.async.commit_group;");
}
template <int N>
__device__ __forceinline__ void cp_wait() {
    asm volatile("cp.async.wait_group %0;" :: "n"(N));
}

__device__ __forceinline__ void ldsm4(uint32_t* r, uint32_t addr) {
    asm volatile("ldmatrix.sync.aligned.m8n8.x4.shared.b16 {%0,%1,%2,%3}, [%4];"
                 : "=r"(r[0]), "=r"(r[1]), "=r"(r[2]), "=r"(r[3]) : "r"(addr));
}

__device__ __forceinline__ void mma16816(float* c, const uint32_t* a,
                                         uint32_t b0, uint32_t b1) {
    asm volatile(
        "mma.sync.aligned.m16n8k16.row.col.f32.f16.f16.f32 "
        "{%0,%1,%2,%3}, {%4,%5,%6,%7}, {%8,%9}, {%0,%1,%2,%3};"
        : "+f"(c[0]), "+f"(c[1]), "+f"(c[2]), "+f"(c[3])
        : "r"(a[0]), "r"(a[1]), "r"(a[2]), "r"(a[3]), "r"(b0), "r"(b1));
}

__device__ __forceinline__ uint32_t pack2h(__half a, __half b) {
    return (uint32_t)__half_as_ushort(a) |
           ((uint32_t)__half_as_ushort(b) << 16);
}

// ---------------------- prep kernels ---------------------------------------
__global__ void __launch_bounds__(256)
prep_A(const int* __restrict__ e1, const int* __restrict__ r,
       const float* __restrict__ ent_re, const float* __restrict__ ent_im,
       const float* __restrict__ phase) {
    const int b = blockIdx.x;
    const int e = e1[b];
    const int rl = r[b];
    const float* hr = ent_re + (size_t)e * DIM;
    const float* hm = ent_im + (size_t)e * DIM;
    const float* ph = phase + (size_t)rl * DIM;
    for (int d = threadIdx.x; d < DIM; d += 256) {
        float a = hr[d], bb = hm[d], p = ph[d];
        float sn, cs;
        sincosf(p, &sn, &cs);
        float sre = a * cs - bb * sn;
        float sim = a * sn + bb * cs;
        __half h0 = __float2half_rn(sre);
        __half l0 = __float2half_rn(sre - __half2float(h0));
        __half h1 = __float2half_rn(sim);
        __half l1 = __float2half_rn(sim - __half2float(h1));
        size_t o = (size_t)b * K2 + d;
        g_A_hi[o] = h0;        g_A_lo[o] = l0;
        g_A_hi[o + DIM] = h1;  g_A_lo[o + DIM] = l1;
    }
}

__global__ void __launch_bounds__(256)
prep_B(const float* __restrict__ ent_re, const float* __restrict__ ent_im) {
    const int n = blockIdx.x;
#pragma unroll
    for (int j = 0; j < 2; ++j) {
        int idx = threadIdx.x + j * 256;            // 0..511 float4 slots
        const float* src = (idx < 256)
            ? ent_re + (size_t)n * DIM + idx * 4
            : ent_im + (size_t)n * DIM + (idx - 256) * 4;
        float4 v = *(const float4*)src;
        uint2 hp;
        hp.x = pack2h(__float2half_rn(v.x), __float2half_rn(v.y));
        hp.y = pack2h(__float2half_rn(v.z), __float2half_rn(v.w));
        *(uint2*)(g_B + (size_t)n * K2 + (size_t)idx * 4) = hp;
    }
}

// ---------------------- GEMM kernel ----------------------------------------
__global__ void __launch_bounds__(256, 2)
gemm_kernel(float* __restrict__ out) {
    extern __shared__ char smem[];
    const uint32_t sb0 = smem_u32(smem);

    const int tid = threadIdx.x;
    const int lane = tid & 31;
    const int wid = tid >> 5;
    const int wm = wid & 1;        // 2 M-blocks of 64
    const int wn = wid >> 1;       // 4 N-blocks of 32
    const int m0 = blockIdx.x * TILE_M;
    const int n0 = blockIdx.y * TILE_N;

    // cp.async addressing: each thread covers 2 rows x 16B per tile
    const int row0 = tid >> 2;     // 0..63
    const int c16 = tid & 3;

    // ldmatrix base offsets within a stage (validated in R3)
    const uint32_t aRow = (uint32_t)((wm * 64 + (lane & 15)) * PITCH + (lane >> 4) * 16);
    const uint32_t bRow = (uint32_t)((wn * 32 + (lane & 15)) * PITCH + (lane >> 4) * 16);

    float acc[4][4][4];
#pragma unroll
    for (int a = 0; a < 4; ++a)
#pragma unroll
        for (int b = 0; b < 4; ++b)
#pragma unroll
            for (int c = 0; c < 4; ++c) acc[a][b][c] = 0.f;

    // ---- load one K-chunk into stage i%NSTAGE ----
    auto load_chunk = [&](int i) {
        const uint32_t sb = sb0 + (i % NSTAGE) * STG;
        const int kc = i * KC;
#pragma unroll
        for (int j = 0; j < 2; ++j) {
            const int row = row0 + j * 64;
            const uint32_t so = (uint32_t)(row * PITCH + c16 * 16);
            const size_t ga = (size_t)(m0 + row) * K2 + kc + c16 * 8;
            cpasync16(sb + so,           g_A_hi + ga);
            cpasync16(sb + TSZ + so,     g_A_lo + ga);
            int n = n0 + row;
            if (n > N_ENT - 1) n = N_ENT - 1;
            const size_t gb = (size_t)n * K2 + kc + c16 * 8;
            cpasync16(sb + 2 * TSZ + so, g_B + gb);
        }
    };

    load_chunk(0); cp_commit();
    load_chunk(1); cp_commit();

    for (int i = 0; i < NCH; ++i) {
        cp_wait<1>();              // group i complete (stage i%3 ready)
        __syncthreads();           // prior iter's reads of stage (i+2)%3 done

        if (i + 2 < NCH) load_chunk(i + 2);
        cp_commit();               // commit (possibly empty) group i+2

        const uint32_t sb = sb0 + (i % NSTAGE) * STG;
#pragma unroll
        for (int kk = 0; kk < 2; ++kk) {
            const uint32_t ko = kk * 32;
            uint32_t ah[4][4], al[4][4], bh[2][4];
#pragma unroll
            for (int mi = 0; mi < 4; ++mi)
                ldsm4(ah[mi], sb + aRow + mi * (16 * PITCH) + ko);
#pragma unroll
            for (int p = 0; p < 2; ++p)
                ldsm4(bh[p], sb + 2 * TSZ + bRow + p * (16 * PITCH) + ko);
            // pass 1: Ah * B
#pragma unroll
            for (int mi = 0; mi < 4; ++mi)
#pragma unroll
                for (int p = 0; p < 2; ++p) {
                    mma16816(acc[mi][2 * p],     ah[mi], bh[p][0], bh[p][2]);
                    mma16816(acc[mi][2 * p + 1], ah[mi], bh[p][1], bh[p][3]);
                }
            // pass 2: Al * B
#pragma unroll
            for (int mi = 0; mi < 4; ++mi)
                ldsm4(al[mi], sb + TSZ + aRow + mi * (16 * PITCH) + ko);
#pragma unroll
            for (int mi = 0; mi < 4; ++mi)
#pragma unroll
                for (int p = 0; p < 2; ++p) {
                    mma16816(acc[mi][2 * p],     al[mi], bh[p][0], bh[p][2]);
                    mma16816(acc[mi][2 * p + 1], al[mi], bh[p][1], bh[p][3]);
                }
        }
    }

    // ---- epilogue ----
    const int mrow = m0 + wm * 64 + (lane >> 2);
    const int ncol = n0 + wn * 32 + (lane & 3) * 2;
#pragma unroll
    for (int mi = 0; mi < 4; ++mi) {
#pragma unroll
        for (int ni = 0; ni < 4; ++ni) {
            const int col = ncol + ni * 8;
            if (col < N_ENT) {
                const int r0 = mrow + mi * 16;
                float2 v0 = make_float2(acc[mi][ni][0], acc[mi][ni][1]);
                float2 v1 = make_float2(acc[mi][ni][2], acc[mi][ni][3]);
                *(float2*)(out + (size_t)r0 * N_ENT + col) = v0;
                *(float2*)(out + (size_t)(r0 + 8) * N_ENT + col) = v1;
            }
        }
    }
}

// ---------------------------- launch ---------------------------------------
extern "C" void kernel_launch(void* const* d_in, const int* in_sizes, int n_in,
                              void* d_out, int out_size) {
    const int*   e1     = (const int*)d_in[0];
    const int*   r      = (const int*)d_in[1];
    const float* ent_re = (const float*)d_in[2];
    const float* ent_im = (const float*)d_in[3];
    const float* phase  = (const float*)d_in[4];
    float* out = (float*)d_out;

    prep_A<<<BATCH, 256>>>(e1, r, ent_re, ent_im, phase);
    prep_B<<<N_ENT, 256>>>(ent_re, ent_im);

    cudaFuncSetAttribute(gemm_kernel,
                         cudaFuncAttributeMaxDynamicSharedMemorySize, SMEM_DYN);
    // m-tiles fastest: 8 CTAs sharing one entity tile are wave-co-resident,
    // so entity data is read ~once from DRAM and reused 8x through L2.
    dim3 grid(BATCH / TILE_M, (N_ENT + TILE_N - 1) / TILE_N);
    gemm_kernel<<<grid, 256, SMEM_DYN>>>(out);
}

// round 5
// speedup vs baseline: 2.7622x; 1.8925x over previous
#include <cuda_runtime.h>
#include <cuda_fp16.h>
#include <cstdint>
#include <cstddef>

// ---------------------------------------------------------------------------
// RotatE scoring on base-target sm_103 (no tcgen05 on base target):
//   C[b,n] = sum_d( sre[b,d]*ent_re[n,d] + sim[b,d]*ent_im[n,d] )
// SINGLE-PASS fp16 GEMM (fp32 accum, mma.sync m16n8k16).
//   Error model (calibrated on R4 measurement): B-rounding alone gave
//   2.07e-4 norm-rel; adding A-rounding gives ~2.9e-4 < 1e-3 threshold.
//   M=1024, N=100000, K=2048 (re||im concat).
// prep_A: gather + sincos + rotate -> g_A (fp16)
// prep_B: entity tables f32 -> fp16 -> g_B
// gemm  : 128x128 tile, 4-stage cp.async pipeline, ldmatrix + mma.sync
//         (fragment mappings validated in R3/R4)
// ---------------------------------------------------------------------------

#define N_ENT   100000
#define DIM     1024
#define BATCH   1024
#define K2      2048

#define TILE_M  128
#define TILE_N  128
#define KC      32
#define NCH     (K2 / KC)        // 64
#define PITCH   80               // SMEM row pitch (bytes): conflict-free ldmatrix
#define TSZ     (TILE_M * PITCH) // 10240 per tile
#define STG     (2 * TSZ)        // A, B -> 20480
#define NSTAGE  4
#define SMEM_DYN (NSTAGE * STG)  // 81920

__device__ __half g_A[(size_t)BATCH * K2];
__device__ __half g_B[(size_t)N_ENT * K2];

// ---------------------------- helpers --------------------------------------
__device__ __forceinline__ uint32_t smem_u32(const void* p) {
    uint32_t a;
    asm("{ .reg .u64 t; cvta.to.shared.u64 t, %1; cvt.u32.u64 %0, t; }"
        : "=r"(a) : "l"(p));
    return a;
}

__device__ __forceinline__ void cpasync16(uint32_t s, const void* g) {
    asm volatile("cp.async.cg.shared.global [%0], [%1], 16;"
                 :: "r"(s), "l"(__cvta_generic_to_global(g)));
}
__device__ __forceinline__ void cp_commit() {
    asm volatile("cp.async.commit_group;");
}
template <int N>
__device__ __forceinline__ void cp_wait() {
    asm volatile("cp.async.wait_group %0;" :: "n"(N));
}

__device__ __forceinline__ void ldsm4(uint32_t* r, uint32_t addr) {
    asm volatile("ldmatrix.sync.aligned.m8n8.x4.shared.b16 {%0,%1,%2,%3}, [%4];"
                 : "=r"(r[0]), "=r"(r[1]), "=r"(r[2]), "=r"(r[3]) : "r"(addr));
}

__device__ __forceinline__ void mma16816(float* c, const uint32_t* a,
                                         uint32_t b0, uint32_t b1) {
    asm volatile(
        "mma.sync.aligned.m16n8k16.row.col.f32.f16.f16.f32 "
        "{%0,%1,%2,%3}, {%4,%5,%6,%7}, {%8,%9}, {%0,%1,%2,%3};"
        : "+f"(c[0]), "+f"(c[1]), "+f"(c[2]), "+f"(c[3])
        : "r"(a[0]), "r"(a[1]), "r"(a[2]), "r"(a[3]), "r"(b0), "r"(b1));
}

__device__ __forceinline__ uint32_t pack2h(__half a, __half b) {
    return (uint32_t)__half_as_ushort(a) |
           ((uint32_t)__half_as_ushort(b) << 16);
}

// ---------------------- prep kernels ---------------------------------------
__global__ void __launch_bounds__(256)
prep_A(const int* __restrict__ e1, const int* __restrict__ r,
       const float* __restrict__ ent_re, const float* __restrict__ ent_im,
       const float* __restrict__ phase) {
    const int b = blockIdx.x;
    const int e = e1[b];
    const int rl = r[b];
    const float* hr = ent_re + (size_t)e * DIM;
    const float* hm = ent_im + (size_t)e * DIM;
    const float* ph = phase + (size_t)rl * DIM;
    for (int d = threadIdx.x; d < DIM; d += 256) {
        float a = hr[d], bb = hm[d], p = ph[d];
        float sn, cs;
        sincosf(p, &sn, &cs);
        float sre = a * cs - bb * sn;
        float sim = a * sn + bb * cs;
        size_t o = (size_t)b * K2 + d;
        g_A[o]       = __float2half_rn(sre);
        g_A[o + DIM] = __float2half_rn(sim);
    }
}

__global__ void __launch_bounds__(256)
prep_B(const float* __restrict__ ent_re, const float* __restrict__ ent_im) {
    const int n = blockIdx.x;
#pragma unroll
    for (int j = 0; j < 2; ++j) {
        int idx = threadIdx.x + j * 256;            // 0..511 float4 slots
        const float* src = (idx < 256)
            ? ent_re + (size_t)n * DIM + idx * 4
            : ent_im + (size_t)n * DIM + (idx - 256) * 4;
        float4 v = *(const float4*)src;
        uint2 hp;
        hp.x = pack2h(__float2half_rn(v.x), __float2half_rn(v.y));
        hp.y = pack2h(__float2half_rn(v.z), __float2half_rn(v.w));
        *(uint2*)(g_B + (size_t)n * K2 + (size_t)idx * 4) = hp;
    }
}

// ---------------------- GEMM kernel ----------------------------------------
__global__ void __launch_bounds__(256, 2)
gemm_kernel(float* __restrict__ out) {
    extern __shared__ char smem[];
    const uint32_t sb0 = smem_u32(smem);

    const int tid = threadIdx.x;
    const int lane = tid & 31;
    const int wid = tid >> 5;
    const int wm = wid & 1;        // 2 M-blocks of 64
    const int wn = wid >> 1;       // 4 N-blocks of 32
    const int m0 = blockIdx.x * TILE_M;
    const int n0 = blockIdx.y * TILE_N;

    // cp.async addressing: each thread covers 2 rows x 16B per tile
    const int row0 = tid >> 2;     // 0..63
    const int c16 = tid & 3;

    // ldmatrix base offsets within a stage (validated in R3/R4)
    const uint32_t aRow = (uint32_t)((wm * 64 + (lane & 15)) * PITCH + (lane >> 4) * 16);
    const uint32_t bRow = (uint32_t)((wn * 32 + (lane & 15)) * PITCH + (lane >> 4) * 16);

    float acc[4][4][4];
#pragma unroll
    for (int a = 0; a < 4; ++a)
#pragma unroll
        for (int b = 0; b < 4; ++b)
#pragma unroll
            for (int c = 0; c < 4; ++c) acc[a][b][c] = 0.f;

    // ---- load one K-chunk into stage i%NSTAGE ----
    auto load_chunk = [&](int i) {
        const uint32_t sb = sb0 + (i % NSTAGE) * STG;
        const int kc = i * KC;
#pragma unroll
        for (int j = 0; j < 2; ++j) {
            const int row = row0 + j * 64;
            const uint32_t so = (uint32_t)(row * PITCH + c16 * 16);
            const size_t ga = (size_t)(m0 + row) * K2 + kc + c16 * 8;
            cpasync16(sb + so, g_A + ga);
            int n = n0 + row;
            if (n > N_ENT - 1) n = N_ENT - 1;
            const size_t gb = (size_t)n * K2 + kc + c16 * 8;
            cpasync16(sb + TSZ + so, g_B + gb);
        }
    };

    load_chunk(0); cp_commit();
    load_chunk(1); cp_commit();
    load_chunk(2); cp_commit();

    for (int i = 0; i < NCH; ++i) {
        cp_wait<2>();              // group i complete (stage i%4 ready)
        __syncthreads();           // all warps done reading stage (i+3)%4's prior use

        if (i + 3 < NCH) load_chunk(i + 3);
        cp_commit();               // commit (possibly empty) group i+3

        const uint32_t sb = sb0 + (i % NSTAGE) * STG;
#pragma unroll
        for (int kk = 0; kk < 2; ++kk) {
            const uint32_t ko = kk * 32;
            uint32_t ah[4][4], bh[2][4];
#pragma unroll
            for (int mi = 0; mi < 4; ++mi)
                ldsm4(ah[mi], sb + aRow + mi * (16 * PITCH) + ko);
#pragma unroll
            for (int p = 0; p < 2; ++p)
                ldsm4(bh[p], sb + TSZ + bRow + p * (16 * PITCH) + ko);
#pragma unroll
            for (int mi = 0; mi < 4; ++mi)
#pragma unroll
                for (int p = 0; p < 2; ++p) {
                    mma16816(acc[mi][2 * p],     ah[mi], bh[p][0], bh[p][2]);
                    mma16816(acc[mi][2 * p + 1], ah[mi], bh[p][1], bh[p][3]);
                }
        }
    }

    // ---- epilogue ----
    const int mrow = m0 + wm * 64 + (lane >> 2);
    const int ncol = n0 + wn * 32 + (lane & 3) * 2;
#pragma unroll
    for (int mi = 0; mi < 4; ++mi) {
#pragma unroll
        for (int ni = 0; ni < 4; ++ni) {
            const int col = ncol + ni * 8;
            if (col < N_ENT) {
                const int r0 = mrow + mi * 16;
                float2 v0 = make_float2(acc[mi][ni][0], acc[mi][ni][1]);
                float2 v1 = make_float2(acc[mi][ni][2], acc[mi][ni][3]);
                *(float2*)(out + (size_t)r0 * N_ENT + col) = v0;
                *(float2*)(out + (size_t)(r0 + 8) * N_ENT + col) = v1;
            }
        }
    }
}

// ---------------------------- launch ---------------------------------------
extern "C" void kernel_launch(void* const* d_in, const int* in_sizes, int n_in,
                              void* d_out, int out_size) {
    const int*   e1     = (const int*)d_in[0];
    const int*   r      = (const int*)d_in[1];
    const float* ent_re = (const float*)d_in[2];
    const float* ent_im = (const float*)d_in[3];
    const float* phase  = (const float*)d_in[4];
    float* out = (float*)d_out;

    prep_A<<<BATCH, 256>>>(e1, r, ent_re, ent_im, phase);
    prep_B<<<N_ENT, 256>>>(ent_re, ent_im);

    cudaFuncSetAttribute(gemm_kernel,
                         cudaFuncAttributeMaxDynamicSharedMemorySize, SMEM_DYN);
    // m-tiles fastest: 8 CTAs sharing one entity tile are wave-co-resident,
    // so entity data is read ~once from DRAM and reused 8x through L2.
    dim3 grid(BATCH / TILE_M, (N_ENT + TILE_N - 1) / TILE_N);
    gemm_kernel<<<grid, 256, SMEM_DYN>>>(out);
}